// round 9
// baseline (speedup 1.0000x reference)
#include <cuda_runtime.h>
#include <cuda_bf16.h>

// HierarchicalDistanceLoss: B=1048576 rows, C=40 classes.
// out[0] = mean(ce * df) ; out[1..B] = df, when out_size > B.
//
// Single fused kernel, 4096 blocks x 256 threads, 256 rows/block:
//   - labels LDG issued before the staging loop (latency overlapped).
//   - Stage 256x40 f32 logits tile into smem via coalesced float4 loads,
//     pitch 44 floats (176B, 16B-aligned, LDS.128 bank-conflict-free).
//   - TWO-PASS compute (R7 semantics: short dependency chains):
//     pass 1: 10x LDS.128 -> max/argmax (strict '>', first max);
//     pass 2: 10x LDS.128 -> sum(exp(x-m)) with 4 INDEPENDENT partial
//     accumulators (FADD chain 10 deep instead of 40).
//   - ce = m + log(S) - x[lbl]; df = dis[lbl*40+am] + 0.5.
//   - __launch_bounds__(256, 5): 5 CTAs/SM (smem 45KB*5=225<=228KB), occ 62.5%.
//   - Deterministic fused reduction: block partial -> g_hdl_partials; last
//     block (atomic ticket, self-resetting) sums 4096 partials in fixed
//     order -> out[0]. Bitwise identical on every graph replay.

#define HDL_B 1048576
#define HDL_C 40
#define HDL_BLOCKS 4096
#define HDL_TPB 256
#define HDL_PITCH 44  // floats; 176B rows, 16B aligned, LDS.128 conflict-free

__device__ float g_hdl_partials[HDL_BLOCKS];
__device__ unsigned int g_hdl_ticket;  // zero-init; self-resetting

__global__ __launch_bounds__(HDL_TPB, 5) void hdl_fused_kernel(
    const float* __restrict__ logits,
    const int* __restrict__ labels,
    const float* __restrict__ dis,
    float* __restrict__ out,
    int df_offset, int store_df, int write_loss)
{
    __shared__ float s[HDL_TPB * HDL_PITCH];   // 256*44*4 = 45056 B
    __shared__ float wsum[HDL_TPB / 32];
    __shared__ int s_is_last;

    const int tid = threadIdx.x;
    const long long row_base = (long long)blockIdx.x * HDL_TPB;
    const long long grow = row_base + tid;

    // Issue label load early; latency hides under the staging loop.
    const int lbl = __ldg(&labels[grow]);

    // ---- coalesced staged load: 256 rows * 10 float4 each ----
    const float4* g4 = reinterpret_cast<const float4*>(logits) + row_base * (HDL_C / 4);
    #pragma unroll
    for (int k = 0; k < 10; k++) {
        int idx = k * HDL_TPB + tid;          // contiguous across warp
        int row = idx / 10;
        int q   = idx % 10;
        float4 v = __ldcs(&g4[idx]);          // streaming: no reuse
        *reinterpret_cast<float4*>(&s[row * HDL_PITCH + q * 4]) = v;
    }
    __syncthreads();

    const float4* xv = reinterpret_cast<const float4*>(&s[tid * HDL_PITCH]);

    // ---- pass 1: max / argmax (strict '>' keeps FIRST max) ----
    float m = -3.402823466e+38f;
    int am = 0;
    #pragma unroll
    for (int q = 0; q < 10; q++) {
        float4 v = xv[q];
        if (v.x > m) { m = v.x; am = q * 4 + 0; }
        if (v.y > m) { m = v.y; am = q * 4 + 1; }
        if (v.z > m) { m = v.z; am = q * 4 + 2; }
        if (v.w > m) { m = v.w; am = q * 4 + 3; }
    }

    // ---- pass 2: sum(exp(x-m)), 4 independent accumulators ----
    float s0 = 0.0f, s1 = 0.0f, s2 = 0.0f, s3 = 0.0f;
    #pragma unroll
    for (int q = 0; q < 10; q++) {
        float4 v = xv[q];
        s0 += __expf(v.x - m);
        s1 += __expf(v.y - m);
        s2 += __expf(v.z - m);
        s3 += __expf(v.w - m);
    }
    const float ssum = (s0 + s1) + (s2 + s3);

    const float xl = s[tid * HDL_PITCH + lbl];        // single scalar LDS
    const float ce = m + __logf(ssum) - xl;
    const float df = __ldg(&dis[lbl * HDL_C + am]) + 0.5f;

    if (store_df) __stcs(&out[df_offset + grow], df);

    // ---- deterministic block reduction of ce*df ----
    float val = ce * df;
    #pragma unroll
    for (int o = 16; o > 0; o >>= 1)
        val += __shfl_down_sync(0xFFFFFFFFu, val, o);
    if ((tid & 31) == 0) wsum[tid >> 5] = val;
    __syncthreads();
    if (tid == 0) {
        float acc = 0.0f;
        #pragma unroll
        for (int w = 0; w < HDL_TPB / 32; w++) acc += wsum[w];
        g_hdl_partials[blockIdx.x] = acc;
        __threadfence();
        unsigned int t = atomicAdd(&g_hdl_ticket, 1u);
        s_is_last = (t == (unsigned int)(HDL_BLOCKS - 1)) ? 1 : 0;
    }
    __syncthreads();

    // ---- last block: reduce 4096 partials in fixed order ----
    if (s_is_last) {
        float acc = 0.0f;
        #pragma unroll
        for (int i = 0; i < HDL_BLOCKS / HDL_TPB; i++) {
            float p;
            asm volatile("ld.global.cg.f32 %0, [%1];"
                         : "=f"(p) : "l"(&g_hdl_partials[tid + i * HDL_TPB]));
            acc += p;
        }
        #pragma unroll
        for (int o = 16; o > 0; o >>= 1)
            acc += __shfl_down_sync(0xFFFFFFFFu, acc, o);
        if ((tid & 31) == 0) wsum[tid >> 5] = acc;
        __syncthreads();
        if (tid == 0) {
            float tot = 0.0f;
            #pragma unroll
            for (int w = 0; w < HDL_TPB / 32; w++) tot += wsum[w];
            if (write_loss) out[0] = tot * (1.0f / (float)HDL_B);
            g_hdl_ticket = 0;   // reset for next graph replay
        }
    }
}

extern "C" void kernel_launch(void* const* d_in, const int* in_sizes, int n_in,
                              void* d_out, int out_size)
{
    const float* logits = (const float*)d_in[0];
    const int*   labels = (const int*)d_in[1];
    const float* dis    = (const float*)d_in[2];
    float* out = (float*)d_out;

    const int has_loss = (out_size != HDL_B) ? 1 : 0;
    const int df_off   = (out_size > HDL_B) ? 1 : 0;
    const int store_df = (out_size >= HDL_B) ? 1 : 0;

    hdl_fused_kernel<<<HDL_BLOCKS, HDL_TPB>>>(logits, labels, dis, out,
                                              df_off, store_df, has_loss);
}

// round 10
// speedup vs baseline: 1.0662x; 1.0662x over previous
#include <cuda_runtime.h>
#include <cuda_bf16.h>
#include <cstdint>

// HierarchicalDistanceLoss: B=1048576 rows, C=40 classes.
// out[0] = mean(ce * df) ; out[1..B] = df, when out_size > B.
//
// Single fused kernel, 4096 blocks x 256 threads, 256 rows/block:
//   - labels LDG issued before the staging loop (latency overlapped).
//   - Stage 256x40 f32 logits tile into smem via cp.async.cg 16B copies
//     (global->smem direct, L1 bypassed, no staging registers, full MLP).
//     Pitch 44 floats (176B, 16B-aligned, LDS.128 bank-conflict-free).
//   - Pass 1: 10x LDS.128 -> max/argmax (strict '>', first max).
//   - Pass 2: 10x LDS.128 -> sum(exp(x-m)). No register array -> no spill.
//   - ce = m + log(S) - x[lbl]; df = dis[lbl*40+am] + 0.5.
//   - NO __launch_bounds__ reg cap (proven harmful in R8/R9); occupancy
//     rises naturally as cp.async frees staging registers.
//   - Deterministic fused reduction: block partial -> g_hdl_partials; last
//     block (atomic ticket, self-resetting) sums 4096 partials in fixed
//     order -> out[0]. Bitwise identical on every graph replay.

#define HDL_B 1048576
#define HDL_C 40
#define HDL_BLOCKS 4096
#define HDL_TPB 256
#define HDL_PITCH 44  // floats; 176B rows, 16B aligned, LDS.128 conflict-free

__device__ float g_hdl_partials[HDL_BLOCKS];
__device__ unsigned int g_hdl_ticket;  // zero-init; self-resetting

__global__ __launch_bounds__(HDL_TPB) void hdl_fused_kernel(
    const float* __restrict__ logits,
    const int* __restrict__ labels,
    const float* __restrict__ dis,
    float* __restrict__ out,
    int df_offset, int store_df, int write_loss)
{
    __shared__ float s[HDL_TPB * HDL_PITCH];   // 256*44*4 = 45056 B
    __shared__ float wsum[HDL_TPB / 32];
    __shared__ int s_is_last;

    const int tid = threadIdx.x;
    const long long row_base = (long long)blockIdx.x * HDL_TPB;
    const long long grow = row_base + tid;

    // Issue label load early; latency hides under the staging copies.
    const int lbl = __ldg(&labels[grow]);

    // ---- staged load via cp.async.cg: 256 rows * 10 x 16B, coalesced ----
    const float4* g4 = reinterpret_cast<const float4*>(logits) + row_base * (HDL_C / 4);
    #pragma unroll
    for (int k = 0; k < 10; k++) {
        int idx = k * HDL_TPB + tid;          // contiguous across warp
        int row = idx / 10;
        int q   = idx % 10;
        uint32_t dst = (uint32_t)__cvta_generic_to_shared(&s[row * HDL_PITCH + q * 4]);
        asm volatile("cp.async.cg.shared.global [%0], [%1], 16;"
                     :: "r"(dst), "l"(&g4[idx]) : "memory");
    }
    asm volatile("cp.async.commit_group;" ::: "memory");
    asm volatile("cp.async.wait_group 0;" ::: "memory");
    __syncthreads();

    const float4* xv = reinterpret_cast<const float4*>(&s[tid * HDL_PITCH]);

    // ---- pass 1: max / argmax (strict '>' keeps FIRST max) ----
    float m = -3.402823466e+38f;
    int am = 0;
    #pragma unroll
    for (int q = 0; q < 10; q++) {
        float4 v = xv[q];
        if (v.x > m) { m = v.x; am = q * 4 + 0; }
        if (v.y > m) { m = v.y; am = q * 4 + 1; }
        if (v.z > m) { m = v.z; am = q * 4 + 2; }
        if (v.w > m) { m = v.w; am = q * 4 + 3; }
    }

    // ---- pass 2: sum(exp(x - m)) ----
    float ssum = 0.0f;
    #pragma unroll
    for (int q = 0; q < 10; q++) {
        float4 v = xv[q];
        ssum += __expf(v.x - m);
        ssum += __expf(v.y - m);
        ssum += __expf(v.z - m);
        ssum += __expf(v.w - m);
    }

    const float xl = s[tid * HDL_PITCH + lbl];        // single scalar LDS
    const float ce = m + __logf(ssum) - xl;
    const float df = __ldg(&dis[lbl * HDL_C + am]) + 0.5f;

    if (store_df) __stcs(&out[df_offset + grow], df);

    // ---- deterministic block reduction of ce*df ----
    float val = ce * df;
    #pragma unroll
    for (int o = 16; o > 0; o >>= 1)
        val += __shfl_down_sync(0xFFFFFFFFu, val, o);
    if ((tid & 31) == 0) wsum[tid >> 5] = val;
    __syncthreads();
    if (tid == 0) {
        float acc = 0.0f;
        #pragma unroll
        for (int w = 0; w < HDL_TPB / 32; w++) acc += wsum[w];
        g_hdl_partials[blockIdx.x] = acc;
        __threadfence();
        unsigned int t = atomicAdd(&g_hdl_ticket, 1u);
        s_is_last = (t == (unsigned int)(HDL_BLOCKS - 1)) ? 1 : 0;
    }
    __syncthreads();

    // ---- last block: reduce 4096 partials in fixed order ----
    if (s_is_last) {
        float acc = 0.0f;
        #pragma unroll
        for (int i = 0; i < HDL_BLOCKS / HDL_TPB; i++) {
            float p;
            asm volatile("ld.global.cg.f32 %0, [%1];"
                         : "=f"(p) : "l"(&g_hdl_partials[tid + i * HDL_TPB]));
            acc += p;
        }
        #pragma unroll
        for (int o = 16; o > 0; o >>= 1)
            acc += __shfl_down_sync(0xFFFFFFFFu, acc, o);
        if ((tid & 31) == 0) wsum[tid >> 5] = acc;
        __syncthreads();
        if (tid == 0) {
            float tot = 0.0f;
            #pragma unroll
            for (int w = 0; w < HDL_TPB / 32; w++) tot += wsum[w];
            if (write_loss) out[0] = tot * (1.0f / (float)HDL_B);
            g_hdl_ticket = 0;   // reset for next graph replay
        }
    }
}

extern "C" void kernel_launch(void* const* d_in, const int* in_sizes, int n_in,
                              void* d_out, int out_size)
{
    const float* logits = (const float*)d_in[0];
    const int*   labels = (const int*)d_in[1];
    const float* dis    = (const float*)d_in[2];
    float* out = (float*)d_out;

    const int has_loss = (out_size != HDL_B) ? 1 : 0;
    const int df_off   = (out_size > HDL_B) ? 1 : 0;
    const int store_df = (out_size >= HDL_B) ? 1 : 0;

    hdl_fused_kernel<<<HDL_BLOCKS, HDL_TPB>>>(logits, labels, dis, out,
                                              df_off, store_df, has_loss);
}

// round 11
// speedup vs baseline: 1.2414x; 1.1644x over previous
#include <cuda_runtime.h>
#include <cuda_bf16.h>
#include <cstdint>

// HierarchicalDistanceLoss: B=1048576 rows, C=40 classes.
// out[0] = mean(ce * df) ; out[1..B] = df, when out_size > B.
//
// PERSISTENT double-buffered kernel: 740 CTAs (5/SM x 148 SMs) x 128 thr.
//   - 8192 tiles of 128 rows; CTA b handles tiles b, b+740, b+1480, ...
//   - Two smem buffers (pitch 44 floats, LDS.128 conflict-free), cp.async.cg
//     prefetch of tile t+1 overlaps compute of tile t -> loads always in
//     flight, no load->barrier->compute serialization, no wave transitions.
//   - Per tile/thread: pass1 max/argmax (strict '>', first max),
//     pass2 sum(exp(x-m)); ce = m + log(S) - x[lbl];
//     df = dis[lbl*40+am] + 0.5 -> streamed to out.
//   - Loss: per-thread accumulator over its tiles (fixed order), ONE block
//     reduction at kernel end -> g_hdl_partials[bid]; last CTA (atomic
//     ticket, self-resetting) sums 740 partials in fixed order -> out[0].
//     Bitwise identical on every graph replay.

#define HDL_B 1048576
#define HDL_C 40
#define HDL_ROWS 128                    // rows per tile
#define HDL_TILES (HDL_B / HDL_ROWS)    // 8192
#define HDL_TPB 128
#define HDL_GRID 740                    // 5 CTAs/SM * 148 SMs
#define HDL_PITCH 44                    // floats; 176B rows, LDS.128 conflict-free

__device__ float g_hdl_partials[HDL_GRID];
__device__ unsigned int g_hdl_ticket;   // zero-init; self-resetting

__device__ __forceinline__ void hdl_prefetch_tile(
    const float4* __restrict__ g4, int tile, float* __restrict__ buf, int tid)
{
    const float4* src = g4 + (long long)tile * (HDL_ROWS * (HDL_C / 4));
    #pragma unroll
    for (int k = 0; k < 10; k++) {
        int idx = k * HDL_TPB + tid;        // 0..1279, contiguous across warp
        int row = idx / 10;
        int q   = idx % 10;
        uint32_t dst = (uint32_t)__cvta_generic_to_shared(&buf[row * HDL_PITCH + q * 4]);
        asm volatile("cp.async.cg.shared.global [%0], [%1], 16;"
                     :: "r"(dst), "l"(&src[idx]) : "memory");
    }
}

__global__ __launch_bounds__(HDL_TPB) void hdl_persist_kernel(
    const float* __restrict__ logits,
    const int* __restrict__ labels,
    const float* __restrict__ dis,
    float* __restrict__ out,
    int df_offset, int store_df, int write_loss)
{
    __shared__ float sbuf[2][HDL_ROWS * HDL_PITCH];  // 2 * 22528B = 45056B
    __shared__ float wsum[HDL_TPB / 32];
    __shared__ int s_is_last;

    const int tid = threadIdx.x;
    const int bid = blockIdx.x;
    const float4* g4 = reinterpret_cast<const float4*>(logits);

    // ---- prologue: prefetch first tile ----
    hdl_prefetch_tile(g4, bid, sbuf[0], tid);
    asm volatile("cp.async.commit_group;" ::: "memory");

    float local = 0.0f;   // per-thread loss accumulator (fixed tile order)

    int i = 0;
    for (int t = bid; t < HDL_TILES; t += HDL_GRID, i++) {
        // prefetch next tile into the other buffer (empty group if none)
        const int tn = t + HDL_GRID;
        if (tn < HDL_TILES)
            hdl_prefetch_tile(g4, tn, sbuf[(i + 1) & 1], tid);
        asm volatile("cp.async.commit_group;" ::: "memory");
        // wait until only the newest group is pending -> tile t resident
        asm volatile("cp.async.wait_group 1;" ::: "memory");
        __syncthreads();

        const long long grow = (long long)t * HDL_ROWS + tid;
        const int lbl = __ldg(&labels[grow]);            // overlaps passes below

        const float* buf = sbuf[i & 1];
        const float4* xv = reinterpret_cast<const float4*>(&buf[tid * HDL_PITCH]);

        // pass 1: max / argmax (strict '>' keeps FIRST max)
        float m = -3.402823466e+38f;
        int am = 0;
        #pragma unroll
        for (int q = 0; q < 10; q++) {
            float4 v = xv[q];
            if (v.x > m) { m = v.x; am = q * 4 + 0; }
            if (v.y > m) { m = v.y; am = q * 4 + 1; }
            if (v.z > m) { m = v.z; am = q * 4 + 2; }
            if (v.w > m) { m = v.w; am = q * 4 + 3; }
        }
        // pass 2: sum(exp(x-m)), independent exps
        float ssum = 0.0f;
        #pragma unroll
        for (int q = 0; q < 10; q++) {
            float4 v = xv[q];
            ssum += __expf(v.x - m);
            ssum += __expf(v.y - m);
            ssum += __expf(v.z - m);
            ssum += __expf(v.w - m);
        }

        const float xl = buf[tid * HDL_PITCH + lbl];     // single scalar LDS
        const float ce = m + __logf(ssum) - xl;
        const float df = __ldg(&dis[lbl * HDL_C + am]) + 0.5f;

        if (store_df) __stcs(&out[df_offset + grow], df);
        local += ce * df;

        __syncthreads();   // compute done before buf is overwritten next iter
    }

    // ---- one block reduction at the end ----
    #pragma unroll
    for (int o = 16; o > 0; o >>= 1)
        local += __shfl_down_sync(0xFFFFFFFFu, local, o);
    if ((tid & 31) == 0) wsum[tid >> 5] = local;
    __syncthreads();
    if (tid == 0) {
        float acc = 0.0f;
        #pragma unroll
        for (int w = 0; w < HDL_TPB / 32; w++) acc += wsum[w];
        g_hdl_partials[bid] = acc;
        __threadfence();
        unsigned int tk = atomicAdd(&g_hdl_ticket, 1u);
        s_is_last = (tk == (unsigned int)(HDL_GRID - 1)) ? 1 : 0;
    }
    __syncthreads();

    // ---- last CTA: reduce 740 partials in fixed order ----
    if (s_is_last) {
        float acc = 0.0f;
        #pragma unroll
        for (int j = 0; j < 6; j++) {                 // 6*128 = 768 >= 740
            int idx = tid + j * HDL_TPB;
            if (idx < HDL_GRID) {
                float p;
                asm volatile("ld.global.cg.f32 %0, [%1];"
                             : "=f"(p) : "l"(&g_hdl_partials[idx]));
                acc += p;
            }
        }
        #pragma unroll
        for (int o = 16; o > 0; o >>= 1)
            acc += __shfl_down_sync(0xFFFFFFFFu, acc, o);
        if ((tid & 31) == 0) wsum[tid >> 5] = acc;
        __syncthreads();
        if (tid == 0) {
            float tot = 0.0f;
            #pragma unroll
            for (int w = 0; w < HDL_TPB / 32; w++) tot += wsum[w];
            if (write_loss) out[0] = tot * (1.0f / (float)HDL_B);
            g_hdl_ticket = 0;   // reset for next graph replay
        }
    }
}

extern "C" void kernel_launch(void* const* d_in, const int* in_sizes, int n_in,
                              void* d_out, int out_size)
{
    const float* logits = (const float*)d_in[0];
    const int*   labels = (const int*)d_in[1];
    const float* dis    = (const float*)d_in[2];
    float* out = (float*)d_out;

    const int has_loss = (out_size != HDL_B) ? 1 : 0;
    const int df_off   = (out_size > HDL_B) ? 1 : 0;
    const int store_df = (out_size >= HDL_B) ? 1 : 0;

    hdl_persist_kernel<<<HDL_GRID, HDL_TPB>>>(logits, labels, dis, out,
                                              df_off, store_df, has_loss);
}